// round 13
// baseline (speedup 1.0000x reference)
#include <cuda_runtime.h>
#include <cstdint>

typedef unsigned long long ull;

#define MAXN 50000

// ---------------- device scratch (no allocations allowed) ----------------
__device__ float g_S   [MAXN * 64];
__device__ float g_deg [MAXN];
__device__ float g_h1  [MAXN * 32];
__device__ float g_h2  [MAXN * 32];
__device__ float g_En  [MAXN * 64];
__device__ float g_Enew[MAXN * 64];

// ---------------- helpers ----------------
__device__ __forceinline__ void fma4(float4& acc, float s, const float4& wv) {
    acc.x += s * wv.x; acc.y += s * wv.y; acc.z += s * wv.z; acc.w += s * wv.w;
}
__device__ __forceinline__ ull pack2(float a, float b) {
    ull r; asm("mov.b64 %0, {%1, %2};" : "=l"(r) : "f"(a), "f"(b)); return r;
}
__device__ __forceinline__ float tanh_fast(float x) {
    float y; asm("tanh.approx.f32 %0, %1;" : "=f"(y) : "f"(x)); return y;
}
__device__ __forceinline__ float rna_tf32(float v) {
    uint32_t r; asm("cvt.rna.tf32.f32 %0, %1;" : "=r"(r) : "f"(v));
    return __uint_as_float(r);
}

// ---------------- kernel 1: per-node h1/h2 = q @ WencP{1,2} + b ----------
__global__ __launch_bounds__(128) void node_pre(
    const float* __restrict__ x,
    const float* __restrict__ W1, const float* __restrict__ b1,
    const float* __restrict__ W2, const float* __restrict__ b2, int n)
{
    __shared__ float4 sW1[32 * 8], sW2[32 * 8], sb1[8], sb2[8];
    for (int i = threadIdx.x; i < 32 * 8; i += 128) {
        sW1[i] = ((const float4*)W1)[i];
        sW2[i] = ((const float4*)W2)[i];
    }
    if (threadIdx.x < 8) {
        sb1[threadIdx.x] = ((const float4*)b1)[threadIdx.x];
        sb2[threadIdx.x] = ((const float4*)b2)[threadIdx.x];
    }
    __syncthreads();
    int i = blockIdx.x * 128 + threadIdx.x;
    if (i >= n) return;

    float q[32];
    const float4* xp = (const float4*)(x + (size_t)i * 64);
#pragma unroll
    for (int k4 = 0; k4 < 8; k4++) {
        float4 v = xp[k4];
        q[4*k4] = v.x; q[4*k4+1] = v.y; q[4*k4+2] = v.z; q[4*k4+3] = v.w;
    }
    float4* o1 = (float4*)(g_h1 + (size_t)i * 32);
    float4* o2 = (float4*)(g_h2 + (size_t)i * 32);
#pragma unroll
    for (int jb = 0; jb < 8; jb++) {
        float4 a1 = sb1[jb], a2 = sb2[jb];
#pragma unroll
        for (int k = 0; k < 32; k++) {
            fma4(a1, q[k], sW1[k*8 + jb]);
            fma4(a2, q[k], sW2[k*8 + jb]);
        }
        o1[jb] = a1;
        o2[jb] = a2;
    }
}

// ---------------- kernel 2: S = segment_sum(x[src], dst), deg ------------
__global__ void edge_scatter(const float* __restrict__ x,
                             const int* __restrict__ src,
                             const int* __restrict__ dst, int e_total)
{
    int t = blockIdx.x * blockDim.x + threadIdx.x;
    int e = t >> 4;
    if (e >= e_total) return;
    int j4 = t & 15;
    int s = __ldg(src + e);
    int d = __ldg(dst + e);
    float4 v = __ldg((const float4*)(x + (size_t)s * 64) + j4);
    atomicAdd((float4*)(g_S + (size_t)d * 64 + j4 * 4), v);
    if (j4 == 0) atomicAdd(&g_deg[d], 1.0f);
}

// ------ kernel 3: hK_agg = S[:,32:]@WencK + deg*b ; E_node = mlp3 --------
__global__ __launch_bounds__(128) void node_mid(
    const float* __restrict__ WencK, const float* __restrict__ bencK,
    const float* __restrict__ WK1, const float* __restrict__ bK1,
    const float* __restrict__ WK2, const float* __restrict__ bK2,
    const float* __restrict__ WK3, const float* __restrict__ bK3, int n)
{
    __shared__ float4 sWe[32 * 8],  sbe[8];
    __shared__ float4 sW1[32 * 16], sb1[16];
    __shared__ float4 sW2[64 * 16], sb2[16];
    __shared__ float4 sW3[64 * 16], sb3[16];
    for (int i = threadIdx.x; i < 32 * 8;  i += 128) sWe[i] = ((const float4*)WencK)[i];
    for (int i = threadIdx.x; i < 32 * 16; i += 128) sW1[i] = ((const float4*)WK1)[i];
    for (int i = threadIdx.x; i < 64 * 16; i += 128) sW2[i] = ((const float4*)WK2)[i];
    for (int i = threadIdx.x; i < 64 * 16; i += 128) sW3[i] = ((const float4*)WK3)[i];
    if (threadIdx.x < 8)  sbe[threadIdx.x] = ((const float4*)bencK)[threadIdx.x];
    if (threadIdx.x < 16) {
        sb1[threadIdx.x] = ((const float4*)bK1)[threadIdx.x];
        sb2[threadIdx.x] = ((const float4*)bK2)[threadIdx.x];
        sb3[threadIdx.x] = ((const float4*)bK3)[threadIdx.x];
    }
    __syncthreads();
    int i = blockIdx.x * 128 + threadIdx.x;
    if (i >= n) return;

    float p[32];
    const float4* Sp = (const float4*)(g_S + (size_t)i * 64);
#pragma unroll
    for (int k4 = 0; k4 < 8; k4++) {
        float4 v = Sp[8 + k4];
        p[4*k4] = v.x; p[4*k4+1] = v.y; p[4*k4+2] = v.z; p[4*k4+3] = v.w;
    }
    float dg = g_deg[i];

    float hK[32];
#pragma unroll
    for (int jb = 0; jb < 8; jb++) {
        float4 b = sbe[jb];
        float4 acc = make_float4(dg*b.x, dg*b.y, dg*b.z, dg*b.w);
#pragma unroll
        for (int k = 0; k < 32; k++) fma4(acc, p[k], sWe[k*8 + jb]);
        hK[4*jb] = acc.x; hK[4*jb+1] = acc.y; hK[4*jb+2] = acc.z; hK[4*jb+3] = acc.w;
    }

    float t1[64];
#pragma unroll
    for (int jb = 0; jb < 16; jb++) {
        float4 acc = sb1[jb];
#pragma unroll
        for (int k = 0; k < 32; k++) fma4(acc, hK[k], sW1[k*16 + jb]);
        t1[4*jb]   = tanh_fast(acc.x); t1[4*jb+1] = tanh_fast(acc.y);
        t1[4*jb+2] = tanh_fast(acc.z); t1[4*jb+3] = tanh_fast(acc.w);
    }

    float t2[64];
#pragma unroll
    for (int jb = 0; jb < 16; jb++) {
        float4 acc = sb2[jb];
#pragma unroll
        for (int k = 0; k < 64; k++) fma4(acc, t1[k], sW2[k*16 + jb]);
        t2[4*jb]   = fmaxf(acc.x, 0.f); t2[4*jb+1] = fmaxf(acc.y, 0.f);
        t2[4*jb+2] = fmaxf(acc.z, 0.f); t2[4*jb+3] = fmaxf(acc.w, 0.f);
    }

    float4* Eo = (float4*)(g_En + (size_t)i * 64);
#pragma unroll
    for (int jb = 0; jb < 16; jb++) {
        float4 acc = sb3[jb];
#pragma unroll
        for (int k = 0; k < 64; k++) fma4(acc, t2[k], sW3[k*16 + jb]);
        Eo[jb] = acc;
    }
}

// =============== kernel 4: mma.sync tf32 edge MLP (2 m-tiles/warp) ========
// 256 threads = 8 warps; tile = 256 edges. Warp w owns rows 32w..32w+31 as
// TWO m16 tiles; each b-fragment LDS.64 feeds 2 mma.sync -> b-frag smem
// traffic per edge halves vs round 12 (L1 was 88% with b-frags dominant).
static constexpr int TILE_E = 256;
static constexpr int ROWA = 68;       // floats per A row (64 + 4 pad)
// smem map (bytes)
static constexpr int OFF_WF1 = 0;        // 32 frags x 256B =  8192
static constexpr int OFF_WF2 = 8192;     // 64 frags x 256B = 16384
static constexpr int OFF_WF3 = 24576;    // 64 frags        = 16384
static constexpr int OFF_B1  = 40960;    // 64 f32
static constexpr int OFF_B2  = 41216;
static constexpr int OFF_B3  = 41472;
static constexpr int OFF_SRC = 41728;    // 256 int = 1024
static constexpr int OFF_DST = 42752;    // 256 int
static constexpr int OFF_A   = 43776;    // 256 x 68 f32 = 69632
static constexpr int EDGE_SMEM = OFF_A + TILE_E * ROWA * 4;   // 113408

__device__ __forceinline__ void mma_tf32(float c[4], uint32_t a0, uint32_t a1,
                                         uint32_t a2, uint32_t a3,
                                         uint32_t b0, uint32_t b1) {
    asm volatile(
        "mma.sync.aligned.m16n8k8.row.col.f32.tf32.tf32.f32 "
        "{%0,%1,%2,%3}, {%4,%5,%6,%7}, {%8,%9}, {%0,%1,%2,%3};"
        : "+f"(c[0]), "+f"(c[1]), "+f"(c[2]), "+f"(c[3])
        : "r"(a0), "r"(a1), "r"(a2), "r"(a3), "r"(b0), "r"(b1));
}

// two m16 tiles (rows rowBase..+15 and rowBase+16..+31) share every b-frag
template<int KC>
__device__ __forceinline__ void layer_mma2(float c0[8][4], float c1[8][4],
                                           const float* sA, const ull* sWf,
                                           const float* sbias, int rowBase,
                                           int lane)
{
    int g = lane >> 2, m = lane & 3;
#pragma unroll
    for (int nc = 0; nc < 8; nc++) {
        float b0 = sbias[nc*8 + 2*m], b1 = sbias[nc*8 + 2*m + 1];
        c0[nc][0] = b0; c0[nc][1] = b1; c0[nc][2] = b0; c0[nc][3] = b1;
        c1[nc][0] = b0; c1[nc][1] = b1; c1[nc][2] = b0; c1[nc][3] = b1;
    }
    const float* r0a = sA + (rowBase + g) * ROWA;
    const float* r0b = sA + (rowBase + g + 8) * ROWA;
    const float* r1a = sA + (rowBase + 16 + g) * ROWA;
    const float* r1b = sA + (rowBase + 24 + g) * ROWA;
#pragma unroll
    for (int kc = 0; kc < KC; kc++) {
        int col = kc*8 + m;
        uint32_t a00 = __float_as_uint(r0a[col]);
        uint32_t a01 = __float_as_uint(r0b[col]);
        uint32_t a02 = __float_as_uint(r0a[col + 4]);
        uint32_t a03 = __float_as_uint(r0b[col + 4]);
        uint32_t a10 = __float_as_uint(r1a[col]);
        uint32_t a11 = __float_as_uint(r1b[col]);
        uint32_t a12 = __float_as_uint(r1a[col + 4]);
        uint32_t a13 = __float_as_uint(r1b[col + 4]);
#pragma unroll
        for (int nc = 0; nc < 8; nc++) {
            ull bb = sWf[(kc*8 + nc) * 32 + lane];
            uint32_t blo = (uint32_t)bb, bhi = (uint32_t)(bb >> 32);
            mma_tf32(c0[nc], a00, a01, a02, a03, blo, bhi);
            mma_tf32(c1[nc], a10, a11, a12, a13, blo, bhi);
        }
    }
}

__global__ void __launch_bounds__(256, 2) edge_mlp(
    const int* __restrict__ src, const int* __restrict__ dst,
    const float* __restrict__ WU1, const float* __restrict__ bU1,
    const float* __restrict__ WU2, const float* __restrict__ bU2,
    const float* __restrict__ WU3, const float* __restrict__ bU3, int e_total)
{
    extern __shared__ char smem[];
    ull* sWf1 = (ull*)(smem + OFF_WF1);
    ull* sWf2 = (ull*)(smem + OFF_WF2);
    ull* sWf3 = (ull*)(smem + OFF_WF3);
    float* sb1 = (float*)(smem + OFF_B1);
    float* sb2 = (float*)(smem + OFF_B2);
    float* sb3 = (float*)(smem + OFF_B3);
    int* sSrc = (int*)(smem + OFF_SRC);
    int* sDst = (int*)(smem + OFF_DST);
    float* sA  = (float*)(smem + OFF_A);

    int tid = threadIdx.x;

    // ---- weights -> fragment order (rna-rounded to tf32) ----
    for (int i = tid; i < 4 * 8 * 32; i += 256) {     // layer1: K=32
        int lane_ = i & 31, f = i >> 5;
        int k0 = (f >> 3) * 8 + (lane_ & 3);
        int n0 = (f & 7) * 8 + (lane_ >> 2);
        sWf1[i] = pack2(rna_tf32(__ldg(WU1 + k0*64 + n0)),
                        rna_tf32(__ldg(WU1 + (k0+4)*64 + n0)));
    }
    for (int i = tid; i < 8 * 8 * 32; i += 256) {     // layers 2,3: K=64
        int lane_ = i & 31, f = i >> 5;
        int k0 = (f >> 3) * 8 + (lane_ & 3);
        int n0 = (f & 7) * 8 + (lane_ >> 2);
        sWf2[i] = pack2(rna_tf32(__ldg(WU2 + k0*64 + n0)),
                        rna_tf32(__ldg(WU2 + (k0+4)*64 + n0)));
        sWf3[i] = pack2(rna_tf32(__ldg(WU3 + k0*64 + n0)),
                        rna_tf32(__ldg(WU3 + (k0+4)*64 + n0)));
    }
    if (tid < 64) {
        sb1[tid] = __ldg(bU1 + tid);
        sb2[tid] = __ldg(bU2 + tid);
        sb3[tid] = __ldg(bU3 + tid);
    }
    __syncthreads();

    int lane = tid & 31, w = tid >> 5;
    int rowBase = w * 32;
    int g = lane >> 2, m = lane & 3;

    int ntiles = (e_total + TILE_E - 1) / TILE_E;
    for (int t = blockIdx.x; t < ntiles; t += gridDim.x) {
        int base = t * TILE_E;

        // ---- gather: one edge per thread, A[tid][0..31] = rna(h1+h2) ----
        {
            int ge = base + tid;
            bool valid = ge < e_total;
            int s = 0, d = 0;
            if (valid) { s = __ldg(src + ge); d = __ldg(dst + ge); }
            sSrc[tid] = s; sDst[tid] = d;
            const float4* h1p = (const float4*)(g_h1 + (size_t)s * 32);
            const float4* h2p = (const float4*)(g_h2 + (size_t)d * 32);
            float* rowp = sA + tid * ROWA;
#pragma unroll
            for (int q = 0; q < 8; q++) {
                float4 a = __ldg(h1p + q), b = __ldg(h2p + q);
                float4 v;
                v.x = valid ? rna_tf32(a.x + b.x) : 0.f;
                v.y = valid ? rna_tf32(a.y + b.y) : 0.f;
                v.z = valid ? rna_tf32(a.z + b.z) : 0.f;
                v.w = valid ? rna_tf32(a.w + b.w) : 0.f;
                *(float4*)(rowp + q * 4) = v;
            }
        }
        __syncthreads();

        float c0[8][4], c1[8][4];

        // ---- layer 1: K=32, tanh ----
        layer_mma2<4>(c0, c1, sA, sWf1, sb1, rowBase, lane);
        __syncthreads();
#pragma unroll
        for (int nc = 0; nc < 8; nc++) {
            int colw = nc*8 + 2*m;
            *(ull*)&sA[(rowBase + g) * ROWA + colw] =
                pack2(rna_tf32(tanh_fast(c0[nc][0])), rna_tf32(tanh_fast(c0[nc][1])));
            *(ull*)&sA[(rowBase + g + 8) * ROWA + colw] =
                pack2(rna_tf32(tanh_fast(c0[nc][2])), rna_tf32(tanh_fast(c0[nc][3])));
            *(ull*)&sA[(rowBase + 16 + g) * ROWA + colw] =
                pack2(rna_tf32(tanh_fast(c1[nc][0])), rna_tf32(tanh_fast(c1[nc][1])));
            *(ull*)&sA[(rowBase + 24 + g) * ROWA + colw] =
                pack2(rna_tf32(tanh_fast(c1[nc][2])), rna_tf32(tanh_fast(c1[nc][3])));
        }
        __syncthreads();

        // ---- layer 2: K=64, relu ----
        layer_mma2<8>(c0, c1, sA, sWf2, sb2, rowBase, lane);
        __syncthreads();
#pragma unroll
        for (int nc = 0; nc < 8; nc++) {
            int colw = nc*8 + 2*m;
            *(ull*)&sA[(rowBase + g) * ROWA + colw] =
                pack2(rna_tf32(fmaxf(c0[nc][0], 0.f)), rna_tf32(fmaxf(c0[nc][1], 0.f)));
            *(ull*)&sA[(rowBase + g + 8) * ROWA + colw] =
                pack2(rna_tf32(fmaxf(c0[nc][2], 0.f)), rna_tf32(fmaxf(c0[nc][3], 0.f)));
            *(ull*)&sA[(rowBase + 16 + g) * ROWA + colw] =
                pack2(rna_tf32(fmaxf(c1[nc][0], 0.f)), rna_tf32(fmaxf(c1[nc][1], 0.f)));
            *(ull*)&sA[(rowBase + 24 + g) * ROWA + colw] =
                pack2(rna_tf32(fmaxf(c1[nc][2], 0.f)), rna_tf32(fmaxf(c1[nc][3], 0.f)));
        }
        __syncthreads();

        // ---- layer 3: K=64 (bias via c-init) ----
        layer_mma2<8>(c0, c1, sA, sWf3, sb3, rowBase, lane);
        __syncthreads();
#pragma unroll
        for (int nc = 0; nc < 8; nc++) {
            int colw = nc*8 + 2*m;
            *(ull*)&sA[(rowBase + g) * ROWA + colw]      = pack2(c0[nc][0], c0[nc][1]);
            *(ull*)&sA[(rowBase + g + 8) * ROWA + colw]  = pack2(c0[nc][2], c0[nc][3]);
            *(ull*)&sA[(rowBase + 16 + g) * ROWA + colw] = pack2(c1[nc][0], c1[nc][1]);
            *(ull*)&sA[(rowBase + 24 + g) * ROWA + colw] = pack2(c1[nc][2], c1[nc][3]);
        }
        __syncthreads();

        // ---- epilogue: one edge per thread: D3 * E_node[src] -> scatter ----
        {
            int ee = tid;
            if (base + ee < e_total) {
                int s = sSrc[ee], d = sDst[ee];
                const float4* Enp = (const float4*)(g_En + (size_t)s * 64);
                float4* Ew = (float4*)(g_Enew + (size_t)d * 64);
                const float* rowp = sA + ee * ROWA;
#pragma unroll
                for (int q = 0; q < 16; q++) {
                    float4 v = *(const float4*)(rowp + q * 4);
                    float4 En = __ldg(Enp + q);
                    v.x *= En.x; v.y *= En.y; v.z *= En.z; v.w *= En.w;
                    atomicAdd(Ew + q, v);
                }
            }
        }
        __syncthreads();   // protect sA/sSrc before next tile's gather
    }
}

// ------ kernel 5: dH = E_new@WH + bH ; d_agg = S@WD[:,32:] + deg*b ; out -
__global__ __launch_bounds__(128) void node_post(
    const float* __restrict__ WH, const float* __restrict__ bH,
    const float* __restrict__ WD, const float* __restrict__ bD,
    float* __restrict__ out, int n)
{
    __shared__ float4 sWH[64 * 16], sbH[16];
    __shared__ float4 sWD[64 * 8],  sbD[8];
    for (int i = threadIdx.x; i < 64 * 16; i += 128) sWH[i] = ((const float4*)WH)[i];
    for (int i = threadIdx.x; i < 64 * 8; i += 128) {
        int k = i >> 3, jb = i & 7;
        sWD[i] = ((const float4*)(WD + k * 64 + 32))[jb];
    }
    if (threadIdx.x < 16) sbH[threadIdx.x] = ((const float4*)bH)[threadIdx.x];
    if (threadIdx.x < 8)  sbD[threadIdx.x] = ((const float4*)(bD + 32))[threadIdx.x];
    __syncthreads();
    int i = blockIdx.x * 128 + threadIdx.x;
    if (i >= n) return;

    float En[64];
    const float4* Ep = (const float4*)(g_Enew + (size_t)i * 64);
#pragma unroll
    for (int k4 = 0; k4 < 16; k4++) {
        float4 v = Ep[k4];
        En[4*k4] = v.x; En[4*k4+1] = v.y; En[4*k4+2] = v.z; En[4*k4+3] = v.w;
    }

    float4* op = (float4*)(out + (size_t)i * 64);
    float dlo[32];
#pragma unroll
    for (int jb = 0; jb < 16; jb++) {
        float4 acc = sbH[jb];
#pragma unroll
        for (int k = 0; k < 64; k++) fma4(acc, En[k], sWH[k*16 + jb]);
        if (jb >= 8) {
            op[jb - 8] = acc;
        } else {
            dlo[4*jb] = acc.x; dlo[4*jb+1] = acc.y;
            dlo[4*jb+2] = acc.z; dlo[4*jb+3] = acc.w;
        }
    }

    float S[64];
    const float4* Sp = (const float4*)(g_S + (size_t)i * 64);
#pragma unroll
    for (int k4 = 0; k4 < 16; k4++) {
        float4 v = Sp[k4];
        S[4*k4] = v.x; S[4*k4+1] = v.y; S[4*k4+2] = v.z; S[4*k4+3] = v.w;
    }
    float dg = g_deg[i];
#pragma unroll
    for (int jb = 0; jb < 8; jb++) {
        float4 b = sbD[jb];
        float4 acc = make_float4(dg*b.x, dg*b.y, dg*b.z, dg*b.w);
#pragma unroll
        for (int k = 0; k < 64; k++) fma4(acc, S[k], sWD[k*8 + jb]);
        float4 o;
        o.x = -dlo[4*jb]   - acc.x;
        o.y = -dlo[4*jb+1] - acc.y;
        o.z = -dlo[4*jb+2] - acc.z;
        o.w = -dlo[4*jb+3] - acc.w;
        op[8 + jb] = o;
    }
}

// -------------------------------------------------------------------------
extern "C" void kernel_launch(void* const* d_in, const int* in_sizes, int n_in,
                              void* d_out, int out_size)
{
    const float* x      = (const float*)d_in[0];
    const int*   src    = (const int*)  d_in[1];
    const int*   dst    = (const int*)  d_in[2];
    const float* WencK  = (const float*)d_in[3];
    const float* bencK  = (const float*)d_in[4];
    const float* WencP1 = (const float*)d_in[5];
    const float* bencP1 = (const float*)d_in[6];
    const float* WencP2 = (const float*)d_in[7];
    const float* bencP2 = (const float*)d_in[8];
    const float* WK1 = (const float*)d_in[9];
    const float* bK1 = (const float*)d_in[10];
    const float* WK2 = (const float*)d_in[11];
    const float* bK2 = (const float*)d_in[12];
    const float* WK3 = (const float*)d_in[13];
    const float* bK3 = (const float*)d_in[14];
    const float* WU1 = (const float*)d_in[15];
    const float* bU1 = (const float*)d_in[16];
    const float* WU2 = (const float*)d_in[17];
    const float* bU2 = (const float*)d_in[18];
    const float* WU3 = (const float*)d_in[19];
    const float* bU3 = (const float*)d_in[20];
    const float* WH  = (const float*)d_in[21];
    const float* bH  = (const float*)d_in[22];
    const float* WD  = (const float*)d_in[23];
    const float* bD  = (const float*)d_in[24];

    int n = in_sizes[0] / 64;
    int e = in_sizes[1];
    if (n > MAXN) n = MAXN;

    cudaFuncSetAttribute(edge_mlp, cudaFuncAttributeMaxDynamicSharedMemorySize,
                         EDGE_SMEM);

    void *pS, *pdeg, *pEnew;
    cudaGetSymbolAddress(&pS,    g_S);
    cudaGetSymbolAddress(&pdeg,  g_deg);
    cudaGetSymbolAddress(&pEnew, g_Enew);
    cudaMemsetAsync(pS,    0, (size_t)n * 64 * sizeof(float));
    cudaMemsetAsync(pdeg,  0, (size_t)n * sizeof(float));
    cudaMemsetAsync(pEnew, 0, (size_t)n * 64 * sizeof(float));

    int nb = (n + 127) / 128;
    node_pre<<<nb, 128>>>(x, WencP1, bencP1, WencP2, bencP2, n);
    edge_scatter<<<((size_t)e * 16 + 255) / 256, 256>>>(x, src, dst, e);
    node_mid<<<nb, 128>>>(WencK, bencK, WK1, bK1, WK2, bK2, WK3, bK3, n);
    edge_mlp<<<296, 256, EDGE_SMEM>>>(src, dst, WU1, bU1, WU2, bU2, WU3, bU3, e);
    node_post<<<nb, 128>>>(WH, bH, WD, bD, (float*)d_out, n);
}

// round 14
// speedup vs baseline: 1.0377x; 1.0377x over previous
#include <cuda_runtime.h>
#include <cstdint>

typedef unsigned long long ull;

#define MAXN 50000

// ---------------- device scratch (no allocations allowed) ----------------
__device__ float g_S   [MAXN * 64];
__device__ float g_deg [MAXN];
__device__ float g_h1  [MAXN * 32];
__device__ float g_h2  [MAXN * 32];
__device__ float g_En  [MAXN * 64];
__device__ float g_Enew[MAXN * 64];

// ---------------- helpers ----------------
__device__ __forceinline__ void fma4(float4& acc, float s, const float4& wv) {
    acc.x += s * wv.x; acc.y += s * wv.y; acc.z += s * wv.z; acc.w += s * wv.w;
}
__device__ __forceinline__ ull pack2(float a, float b) {
    ull r; asm("mov.b64 %0, {%1, %2};" : "=l"(r) : "f"(a), "f"(b)); return r;
}
__device__ __forceinline__ float tanh_fast(float x) {
    float y; asm("tanh.approx.f32 %0, %1;" : "=f"(y) : "f"(x)); return y;
}
__device__ __forceinline__ float rna_tf32(float v) {
    uint32_t r; asm("cvt.rna.tf32.f32 %0, %1;" : "=r"(r) : "f"(v));
    return __uint_as_float(r);
}

// ---------------- kernel 1: per-node h1/h2 = q @ WencP{1,2} + b ----------
__global__ __launch_bounds__(128) void node_pre(
    const float* __restrict__ x,
    const float* __restrict__ W1, const float* __restrict__ b1,
    const float* __restrict__ W2, const float* __restrict__ b2, int n)
{
    __shared__ float4 sW1[32 * 8], sW2[32 * 8], sb1[8], sb2[8];
    for (int i = threadIdx.x; i < 32 * 8; i += 128) {
        sW1[i] = ((const float4*)W1)[i];
        sW2[i] = ((const float4*)W2)[i];
    }
    if (threadIdx.x < 8) {
        sb1[threadIdx.x] = ((const float4*)b1)[threadIdx.x];
        sb2[threadIdx.x] = ((const float4*)b2)[threadIdx.x];
    }
    __syncthreads();
    int i = blockIdx.x * 128 + threadIdx.x;
    if (i >= n) return;

    float q[32];
    const float4* xp = (const float4*)(x + (size_t)i * 64);
#pragma unroll
    for (int k4 = 0; k4 < 8; k4++) {
        float4 v = xp[k4];
        q[4*k4] = v.x; q[4*k4+1] = v.y; q[4*k4+2] = v.z; q[4*k4+3] = v.w;
    }
    float4* o1 = (float4*)(g_h1 + (size_t)i * 32);
    float4* o2 = (float4*)(g_h2 + (size_t)i * 32);
#pragma unroll
    for (int jb = 0; jb < 8; jb++) {
        float4 a1 = sb1[jb], a2 = sb2[jb];
#pragma unroll
        for (int k = 0; k < 32; k++) {
            fma4(a1, q[k], sW1[k*8 + jb]);
            fma4(a2, q[k], sW2[k*8 + jb]);
        }
        o1[jb] = a1;
        o2[jb] = a2;
    }
}

// ---------------- kernel 2: S = segment_sum(x[src], dst), deg ------------
__global__ void edge_scatter(const float* __restrict__ x,
                             const int* __restrict__ src,
                             const int* __restrict__ dst, int e_total)
{
    int t = blockIdx.x * blockDim.x + threadIdx.x;
    int e = t >> 4;
    if (e >= e_total) return;
    int j4 = t & 15;
    int s = __ldg(src + e);
    int d = __ldg(dst + e);
    float4 v = __ldg((const float4*)(x + (size_t)s * 64) + j4);
    atomicAdd((float4*)(g_S + (size_t)d * 64 + j4 * 4), v);
    if (j4 == 0) atomicAdd(&g_deg[d], 1.0f);
}

// ------ kernel 3: hK_agg = S[:,32:]@WencK + deg*b ; E_node = mlp3 --------
__global__ __launch_bounds__(128) void node_mid(
    const float* __restrict__ WencK, const float* __restrict__ bencK,
    const float* __restrict__ WK1, const float* __restrict__ bK1,
    const float* __restrict__ WK2, const float* __restrict__ bK2,
    const float* __restrict__ WK3, const float* __restrict__ bK3, int n)
{
    __shared__ float4 sWe[32 * 8],  sbe[8];
    __shared__ float4 sW1[32 * 16], sb1[16];
    __shared__ float4 sW2[64 * 16], sb2[16];
    __shared__ float4 sW3[64 * 16], sb3[16];
    for (int i = threadIdx.x; i < 32 * 8;  i += 128) sWe[i] = ((const float4*)WencK)[i];
    for (int i = threadIdx.x; i < 32 * 16; i += 128) sW1[i] = ((const float4*)WK1)[i];
    for (int i = threadIdx.x; i < 64 * 16; i += 128) sW2[i] = ((const float4*)WK2)[i];
    for (int i = threadIdx.x; i < 64 * 16; i += 128) sW3[i] = ((const float4*)WK3)[i];
    if (threadIdx.x < 8)  sbe[threadIdx.x] = ((const float4*)bencK)[threadIdx.x];
    if (threadIdx.x < 16) {
        sb1[threadIdx.x] = ((const float4*)bK1)[threadIdx.x];
        sb2[threadIdx.x] = ((const float4*)bK2)[threadIdx.x];
        sb3[threadIdx.x] = ((const float4*)bK3)[threadIdx.x];
    }
    __syncthreads();
    int i = blockIdx.x * 128 + threadIdx.x;
    if (i >= n) return;

    float p[32];
    const float4* Sp = (const float4*)(g_S + (size_t)i * 64);
#pragma unroll
    for (int k4 = 0; k4 < 8; k4++) {
        float4 v = Sp[8 + k4];
        p[4*k4] = v.x; p[4*k4+1] = v.y; p[4*k4+2] = v.z; p[4*k4+3] = v.w;
    }
    float dg = g_deg[i];

    float hK[32];
#pragma unroll
    for (int jb = 0; jb < 8; jb++) {
        float4 b = sbe[jb];
        float4 acc = make_float4(dg*b.x, dg*b.y, dg*b.z, dg*b.w);
#pragma unroll
        for (int k = 0; k < 32; k++) fma4(acc, p[k], sWe[k*8 + jb]);
        hK[4*jb] = acc.x; hK[4*jb+1] = acc.y; hK[4*jb+2] = acc.z; hK[4*jb+3] = acc.w;
    }

    float t1[64];
#pragma unroll
    for (int jb = 0; jb < 16; jb++) {
        float4 acc = sb1[jb];
#pragma unroll
        for (int k = 0; k < 32; k++) fma4(acc, hK[k], sW1[k*16 + jb]);
        t1[4*jb]   = tanh_fast(acc.x); t1[4*jb+1] = tanh_fast(acc.y);
        t1[4*jb+2] = tanh_fast(acc.z); t1[4*jb+3] = tanh_fast(acc.w);
    }

    float t2[64];
#pragma unroll
    for (int jb = 0; jb < 16; jb++) {
        float4 acc = sb2[jb];
#pragma unroll
        for (int k = 0; k < 64; k++) fma4(acc, t1[k], sW2[k*16 + jb]);
        t2[4*jb]   = fmaxf(acc.x, 0.f); t2[4*jb+1] = fmaxf(acc.y, 0.f);
        t2[4*jb+2] = fmaxf(acc.z, 0.f); t2[4*jb+3] = fmaxf(acc.w, 0.f);
    }

    float4* Eo = (float4*)(g_En + (size_t)i * 64);
#pragma unroll
    for (int jb = 0; jb < 16; jb++) {
        float4 acc = sb3[jb];
#pragma unroll
        for (int k = 0; k < 64; k++) fma4(acc, t2[k], sW3[k*16 + jb]);
        Eo[jb] = acc;
    }
}

// =============== kernel 4: mma.sync tf32 edge MLP =========================
// Round-12 structure (best: 324us) with smem trimmed for 3 blocks/SM:
// sSrc/sDst dropped (epilogue re-reads src/dst via L1-hot __ldg) ->
// EDGE_SMEM 77,568 -> 76,544; 3 x (76,544 + 1,024) = 232,704 <= 233,472.
// 256 threads = 8 warps; tile = 128 edges; warp w owns rows 16w..16w+15.
static constexpr int TILE_E = 128;
static constexpr int ROWA = 68;       // floats per A row (64 + 4 pad)
// smem map (bytes)
static constexpr int OFF_WF1 = 0;        // 32 frags x 256B =  8192
static constexpr int OFF_WF2 = 8192;     // 64 frags x 256B = 16384
static constexpr int OFF_WF3 = 24576;    // 64 frags        = 16384
static constexpr int OFF_B1  = 40960;    // 64 f32
static constexpr int OFF_B2  = 41216;
static constexpr int OFF_B3  = 41472;
static constexpr int OFF_A   = 41728;    // 128 x 68 f32 = 34816
static constexpr int EDGE_SMEM = OFF_A + TILE_E * ROWA * 4;   // 76544

__device__ __forceinline__ void mma_tf32(float c[4], uint32_t a0, uint32_t a1,
                                         uint32_t a2, uint32_t a3,
                                         uint32_t b0, uint32_t b1) {
    asm volatile(
        "mma.sync.aligned.m16n8k8.row.col.f32.tf32.tf32.f32 "
        "{%0,%1,%2,%3}, {%4,%5,%6,%7}, {%8,%9}, {%0,%1,%2,%3};"
        : "+f"(c[0]), "+f"(c[1]), "+f"(c[2]), "+f"(c[3])
        : "r"(a0), "r"(a1), "r"(a2), "r"(a3), "r"(b0), "r"(b1));
}

// one layer: c[nc][4] = bias + A(rows rowBase..+15) @ W ; KC = K/8
template<int KC>
__device__ __forceinline__ void layer_mma(float c[8][4], const float* sA,
                                          const ull* sWf, const float* sbias,
                                          int rowBase, int lane)
{
    int g = lane >> 2, m = lane & 3;
#pragma unroll
    for (int nc = 0; nc < 8; nc++) {
        float b0 = sbias[nc*8 + 2*m], b1 = sbias[nc*8 + 2*m + 1];
        c[nc][0] = b0; c[nc][1] = b1; c[nc][2] = b0; c[nc][3] = b1;
    }
    const float* ra = sA + (rowBase + g) * ROWA;
    const float* rb = sA + (rowBase + g + 8) * ROWA;
#pragma unroll
    for (int kc = 0; kc < KC; kc++) {
        int col = kc*8 + m;
        uint32_t a0 = __float_as_uint(ra[col]);
        uint32_t a1 = __float_as_uint(rb[col]);
        uint32_t a2 = __float_as_uint(ra[col + 4]);
        uint32_t a3 = __float_as_uint(rb[col + 4]);
#pragma unroll
        for (int nc = 0; nc < 8; nc++) {
            ull bb = sWf[(kc*8 + nc) * 32 + lane];
            mma_tf32(c[nc], a0, a1, a2, a3,
                     (uint32_t)bb, (uint32_t)(bb >> 32));
        }
    }
}

__global__ void __launch_bounds__(256, 3) edge_mlp(
    const int* __restrict__ src, const int* __restrict__ dst,
    const float* __restrict__ WU1, const float* __restrict__ bU1,
    const float* __restrict__ WU2, const float* __restrict__ bU2,
    const float* __restrict__ WU3, const float* __restrict__ bU3, int e_total)
{
    extern __shared__ char smem[];
    ull* sWf1 = (ull*)(smem + OFF_WF1);
    ull* sWf2 = (ull*)(smem + OFF_WF2);
    ull* sWf3 = (ull*)(smem + OFF_WF3);
    float* sb1 = (float*)(smem + OFF_B1);
    float* sb2 = (float*)(smem + OFF_B2);
    float* sb3 = (float*)(smem + OFF_B3);
    float* sA  = (float*)(smem + OFF_A);

    int tid = threadIdx.x;

    // ---- weights -> fragment order (rna-rounded to tf32) ----
    // frag f = kc*8+nc; lane holds b0 = W[kc*8 + lane%4][nc*8 + lane/4],
    //                              b1 = W[kc*8 + lane%4 + 4][same n]
    for (int i = tid; i < 4 * 8 * 32; i += 256) {     // layer1: K=32
        int lane_ = i & 31, f = i >> 5;
        int k0 = (f >> 3) * 8 + (lane_ & 3);
        int n0 = (f & 7) * 8 + (lane_ >> 2);
        sWf1[i] = pack2(rna_tf32(__ldg(WU1 + k0*64 + n0)),
                        rna_tf32(__ldg(WU1 + (k0+4)*64 + n0)));
    }
    for (int i = tid; i < 8 * 8 * 32; i += 256) {     // layers 2,3: K=64
        int lane_ = i & 31, f = i >> 5;
        int k0 = (f >> 3) * 8 + (lane_ & 3);
        int n0 = (f & 7) * 8 + (lane_ >> 2);
        sWf2[i] = pack2(rna_tf32(__ldg(WU2 + k0*64 + n0)),
                        rna_tf32(__ldg(WU2 + (k0+4)*64 + n0)));
        sWf3[i] = pack2(rna_tf32(__ldg(WU3 + k0*64 + n0)),
                        rna_tf32(__ldg(WU3 + (k0+4)*64 + n0)));
    }
    if (tid < 64) {
        sb1[tid] = __ldg(bU1 + tid);
        sb2[tid] = __ldg(bU2 + tid);
        sb3[tid] = __ldg(bU3 + tid);
    }
    __syncthreads();

    int lane = tid & 31, w = tid >> 5;
    int rowBase = w * 16;
    int g = lane >> 2, m = lane & 3;
    int eh = tid & 127, half = tid >> 7;   // gather roles

    int ntiles = (e_total + TILE_E - 1) / TILE_E;
    for (int t = blockIdx.x; t < ntiles; t += gridDim.x) {
        int base = t * TILE_E;

        // ---- gather: A[eh][k] = rna(h1[src]+h2[dst]), k = half*16..+15 ----
        {
            int ge = base + eh;
            bool valid = ge < e_total;
            int s = 0, d = 0;
            if (valid) { s = __ldg(src + ge); d = __ldg(dst + ge); }
            const float4* h1p = (const float4*)(g_h1 + (size_t)s * 32) + half * 4;
            const float4* h2p = (const float4*)(g_h2 + (size_t)d * 32) + half * 4;
            float* rowp = sA + eh * ROWA + half * 16;
#pragma unroll
            for (int q = 0; q < 4; q++) {
                float4 a = __ldg(h1p + q), b = __ldg(h2p + q);
                float4 v;
                v.x = valid ? rna_tf32(a.x + b.x) : 0.f;
                v.y = valid ? rna_tf32(a.y + b.y) : 0.f;
                v.z = valid ? rna_tf32(a.z + b.z) : 0.f;
                v.w = valid ? rna_tf32(a.w + b.w) : 0.f;
                *(float4*)(rowp + q * 4) = v;
            }
        }
        __syncthreads();

        float c[8][4];

        // ---- layer 1: K=32, tanh ----
        layer_mma<4>(c, sA, sWf1, sb1, rowBase, lane);
        __syncthreads();
#pragma unroll
        for (int nc = 0; nc < 8; nc++) {
            int colw = nc*8 + 2*m;
            *(ull*)&sA[(rowBase + g) * ROWA + colw] =
                pack2(rna_tf32(tanh_fast(c[nc][0])), rna_tf32(tanh_fast(c[nc][1])));
            *(ull*)&sA[(rowBase + g + 8) * ROWA + colw] =
                pack2(rna_tf32(tanh_fast(c[nc][2])), rna_tf32(tanh_fast(c[nc][3])));
        }
        __syncthreads();

        // ---- layer 2: K=64, relu ----
        layer_mma<8>(c, sA, sWf2, sb2, rowBase, lane);
        __syncthreads();
#pragma unroll
        for (int nc = 0; nc < 8; nc++) {
            int colw = nc*8 + 2*m;
            *(ull*)&sA[(rowBase + g) * ROWA + colw] =
                pack2(rna_tf32(fmaxf(c[nc][0], 0.f)), rna_tf32(fmaxf(c[nc][1], 0.f)));
            *(ull*)&sA[(rowBase + g + 8) * ROWA + colw] =
                pack2(rna_tf32(fmaxf(c[nc][2], 0.f)), rna_tf32(fmaxf(c[nc][3], 0.f)));
        }
        __syncthreads();

        // ---- layer 3: K=64, raw (bias included via c-init) ----
        layer_mma<8>(c, sA, sWf3, sb3, rowBase, lane);
        __syncthreads();
#pragma unroll
        for (int nc = 0; nc < 8; nc++) {
            int colw = nc*8 + 2*m;
            *(ull*)&sA[(rowBase + g) * ROWA + colw]     = pack2(c[nc][0], c[nc][1]);
            *(ull*)&sA[(rowBase + g + 8) * ROWA + colw] = pack2(c[nc][2], c[nc][3]);
        }
        __syncthreads();

        // ---- epilogue: (D3) * E_node[src] -> atomic scatter ----
        // src/dst re-read via __ldg (L1/L2-hot from the gather above).
        {
            int ee = tid >> 1;
            int ch = (tid & 1) * 32;
            if (base + ee < e_total) {
                int s = __ldg(src + base + ee);
                int d = __ldg(dst + base + ee);
                const float4* Enp = (const float4*)(g_En + (size_t)s * 64 + ch);
                float4* Ew = (float4*)(g_Enew + (size_t)d * 64 + ch);
                const float* rowp = sA + ee * ROWA + ch;
#pragma unroll
                for (int q = 0; q < 8; q++) {
                    float4 v = *(const float4*)(rowp + q * 4);
                    float4 En = __ldg(Enp + q);
                    v.x *= En.x; v.y *= En.y; v.z *= En.z; v.w *= En.w;
                    atomicAdd(Ew + q, v);
                }
            }
        }
        __syncthreads();   // protect sA before next tile's gather
    }
}

// ------ kernel 5: dH = E_new@WH + bH ; d_agg = S@WD[:,32:] + deg*b ; out -
__global__ __launch_bounds__(128) void node_post(
    const float* __restrict__ WH, const float* __restrict__ bH,
    const float* __restrict__ WD, const float* __restrict__ bD,
    float* __restrict__ out, int n)
{
    __shared__ float4 sWH[64 * 16], sbH[16];
    __shared__ float4 sWD[64 * 8],  sbD[8];
    for (int i = threadIdx.x; i < 64 * 16; i += 128) sWH[i] = ((const float4*)WH)[i];
    for (int i = threadIdx.x; i < 64 * 8; i += 128) {
        int k = i >> 3, jb = i & 7;
        sWD[i] = ((const float4*)(WD + k * 64 + 32))[jb];
    }
    if (threadIdx.x < 16) sbH[threadIdx.x] = ((const float4*)bH)[threadIdx.x];
    if (threadIdx.x < 8)  sbD[threadIdx.x] = ((const float4*)(bD + 32))[threadIdx.x];
    __syncthreads();
    int i = blockIdx.x * 128 + threadIdx.x;
    if (i >= n) return;

    float En[64];
    const float4* Ep = (const float4*)(g_Enew + (size_t)i * 64);
#pragma unroll
    for (int k4 = 0; k4 < 16; k4++) {
        float4 v = Ep[k4];
        En[4*k4] = v.x; En[4*k4+1] = v.y; En[4*k4+2] = v.z; En[4*k4+3] = v.w;
    }

    float4* op = (float4*)(out + (size_t)i * 64);
    float dlo[32];
#pragma unroll
    for (int jb = 0; jb < 16; jb++) {
        float4 acc = sbH[jb];
#pragma unroll
        for (int k = 0; k < 64; k++) fma4(acc, En[k], sWH[k*16 + jb]);
        if (jb >= 8) {
            op[jb - 8] = acc;
        } else {
            dlo[4*jb] = acc.x; dlo[4*jb+1] = acc.y;
            dlo[4*jb+2] = acc.z; dlo[4*jb+3] = acc.w;
        }
    }

    float S[64];
    const float4* Sp = (const float4*)(g_S + (size_t)i * 64);
#pragma unroll
    for (int k4 = 0; k4 < 16; k4++) {
        float4 v = Sp[k4];
        S[4*k4] = v.x; S[4*k4+1] = v.y; S[4*k4+2] = v.z; S[4*k4+3] = v.w;
    }
    float dg = g_deg[i];
#pragma unroll
    for (int jb = 0; jb < 8; jb++) {
        float4 b = sbD[jb];
        float4 acc = make_float4(dg*b.x, dg*b.y, dg*b.z, dg*b.w);
#pragma unroll
        for (int k = 0; k < 64; k++) fma4(acc, S[k], sWD[k*8 + jb]);
        float4 o;
        o.x = -dlo[4*jb]   - acc.x;
        o.y = -dlo[4*jb+1] - acc.y;
        o.z = -dlo[4*jb+2] - acc.z;
        o.w = -dlo[4*jb+3] - acc.w;
        op[8 + jb] = o;
    }
}

// -------------------------------------------------------------------------
extern "C" void kernel_launch(void* const* d_in, const int* in_sizes, int n_in,
                              void* d_out, int out_size)
{
    const float* x      = (const float*)d_in[0];
    const int*   src    = (const int*)  d_in[1];
    const int*   dst    = (const int*)  d_in[2];
    const float* WencK  = (const float*)d_in[3];
    const float* bencK  = (const float*)d_in[4];
    const float* WencP1 = (const float*)d_in[5];
    const float* bencP1 = (const float*)d_in[6];
    const float* WencP2 = (const float*)d_in[7];
    const float* bencP2 = (const float*)d_in[8];
    const float* WK1 = (const float*)d_in[9];
    const float* bK1 = (const float*)d_in[10];
    const float* WK2 = (const float*)d_in[11];
    const float* bK2 = (const float*)d_in[12];
    const float* WK3 = (const float*)d_in[13];
    const float* bK3 = (const float*)d_in[14];
    const float* WU1 = (const float*)d_in[15];
    const float* bU1 = (const float*)d_in[16];
    const float* WU2 = (const float*)d_in[17];
    const float* bU2 = (const float*)d_in[18];
    const float* WU3 = (const float*)d_in[19];
    const float* bU3 = (const float*)d_in[20];
    const float* WH  = (const float*)d_in[21];
    const float* bH  = (const float*)d_in[22];
    const float* WD  = (const float*)d_in[23];
    const float* bD  = (const float*)d_in[24];

    int n = in_sizes[0] / 64;
    int e = in_sizes[1];
    if (n > MAXN) n = MAXN;

    cudaFuncSetAttribute(edge_mlp, cudaFuncAttributeMaxDynamicSharedMemorySize,
                         EDGE_SMEM);

    void *pS, *pdeg, *pEnew;
    cudaGetSymbolAddress(&pS,    g_S);
    cudaGetSymbolAddress(&pdeg,  g_deg);
    cudaGetSymbolAddress(&pEnew, g_Enew);
    cudaMemsetAsync(pS,    0, (size_t)n * 64 * sizeof(float));
    cudaMemsetAsync(pdeg,  0, (size_t)n * sizeof(float));
    cudaMemsetAsync(pEnew, 0, (size_t)n * 64 * sizeof(float));

    int nb = (n + 127) / 128;
    node_pre<<<nb, 128>>>(x, WencP1, bencP1, WencP2, bencP2, n);
    edge_scatter<<<((size_t)e * 16 + 255) / 256, 256>>>(x, src, dst, e);
    node_mid<<<nb, 128>>>(WencK, bencK, WK1, bK1, WK2, bK2, WK3, bK3, n);
    edge_mlp<<<444, 256, EDGE_SMEM>>>(src, dst, WU1, bU1, WU2, bU2, WU3, bU3, e);
    node_post<<<nb, 128>>>(WH, bH, WD, bD, (float*)d_out, n);
}

// round 15
// speedup vs baseline: 1.3034x; 1.2561x over previous
#include <cuda_runtime.h>
#include <cuda_bf16.h>
#include <cstdint>

typedef unsigned long long ull;

#define MAXN 50000

// ---------------- device scratch (no allocations allowed) ----------------
__device__ float g_S   [MAXN * 64];
__device__ float g_deg [MAXN];
__device__ float g_h1  [MAXN * 32];
__device__ float g_h2  [MAXN * 32];
__device__ float g_En  [MAXN * 64];
__device__ float g_Enew[MAXN * 64];

// ---------------- helpers ----------------
__device__ __forceinline__ void fma4(float4& acc, float s, const float4& wv) {
    acc.x += s * wv.x; acc.y += s * wv.y; acc.z += s * wv.z; acc.w += s * wv.w;
}
__device__ __forceinline__ float tanh_fast(float x) {
    float y; asm("tanh.approx.f32 %0, %1;" : "=f"(y) : "f"(x)); return y;
}
// pack two f32 into bf16x2 (lo, hi)
__device__ __forceinline__ uint32_t pack_bf(float lo, float hi) {
    uint32_t r;
    asm("cvt.rn.bf16x2.f32 %0, %1, %2;" : "=r"(r) : "f"(hi), "f"(lo));
    return r;
}
__device__ __forceinline__ float2 unpack_bf(uint32_t v) {
    __nv_bfloat162 h = *reinterpret_cast<__nv_bfloat162*>(&v);
    return __bfloat1622float2(h);
}

// ---------------- kernel 1: per-node h1/h2 = q @ WencP{1,2} + b ----------
__global__ __launch_bounds__(128) void node_pre(
    const float* __restrict__ x,
    const float* __restrict__ W1, const float* __restrict__ b1,
    const float* __restrict__ W2, const float* __restrict__ b2, int n)
{
    __shared__ float4 sW1[32 * 8], sW2[32 * 8], sb1[8], sb2[8];
    for (int i = threadIdx.x; i < 32 * 8; i += 128) {
        sW1[i] = ((const float4*)W1)[i];
        sW2[i] = ((const float4*)W2)[i];
    }
    if (threadIdx.x < 8) {
        sb1[threadIdx.x] = ((const float4*)b1)[threadIdx.x];
        sb2[threadIdx.x] = ((const float4*)b2)[threadIdx.x];
    }
    __syncthreads();
    int i = blockIdx.x * 128 + threadIdx.x;
    if (i >= n) return;

    float q[32];
    const float4* xp = (const float4*)(x + (size_t)i * 64);
#pragma unroll
    for (int k4 = 0; k4 < 8; k4++) {
        float4 v = xp[k4];
        q[4*k4] = v.x; q[4*k4+1] = v.y; q[4*k4+2] = v.z; q[4*k4+3] = v.w;
    }
    float4* o1 = (float4*)(g_h1 + (size_t)i * 32);
    float4* o2 = (float4*)(g_h2 + (size_t)i * 32);
#pragma unroll
    for (int jb = 0; jb < 8; jb++) {
        float4 a1 = sb1[jb], a2 = sb2[jb];
#pragma unroll
        for (int k = 0; k < 32; k++) {
            fma4(a1, q[k], sW1[k*8 + jb]);
            fma4(a2, q[k], sW2[k*8 + jb]);
        }
        o1[jb] = a1;
        o2[jb] = a2;
    }
}

// ---------------- kernel 2: S = segment_sum(x[src], dst), deg ------------
__global__ void edge_scatter(const float* __restrict__ x,
                             const int* __restrict__ src,
                             const int* __restrict__ dst, int e_total)
{
    int t = blockIdx.x * blockDim.x + threadIdx.x;
    int e = t >> 4;
    if (e >= e_total) return;
    int j4 = t & 15;
    int s = __ldg(src + e);
    int d = __ldg(dst + e);
    float4 v = __ldg((const float4*)(x + (size_t)s * 64) + j4);
    atomicAdd((float4*)(g_S + (size_t)d * 64 + j4 * 4), v);
    if (j4 == 0) atomicAdd(&g_deg[d], 1.0f);
}

// ------ kernel 3: hK_agg = S[:,32:]@WencK + deg*b ; E_node = mlp3 --------
__global__ __launch_bounds__(128) void node_mid(
    const float* __restrict__ WencK, const float* __restrict__ bencK,
    const float* __restrict__ WK1, const float* __restrict__ bK1,
    const float* __restrict__ WK2, const float* __restrict__ bK2,
    const float* __restrict__ WK3, const float* __restrict__ bK3, int n)
{
    __shared__ float4 sWe[32 * 8],  sbe[8];
    __shared__ float4 sW1[32 * 16], sb1[16];
    __shared__ float4 sW2[64 * 16], sb2[16];
    __shared__ float4 sW3[64 * 16], sb3[16];
    for (int i = threadIdx.x; i < 32 * 8;  i += 128) sWe[i] = ((const float4*)WencK)[i];
    for (int i = threadIdx.x; i < 32 * 16; i += 128) sW1[i] = ((const float4*)WK1)[i];
    for (int i = threadIdx.x; i < 64 * 16; i += 128) sW2[i] = ((const float4*)WK2)[i];
    for (int i = threadIdx.x; i < 64 * 16; i += 128) sW3[i] = ((const float4*)WK3)[i];
    if (threadIdx.x < 8)  sbe[threadIdx.x] = ((const float4*)bencK)[threadIdx.x];
    if (threadIdx.x < 16) {
        sb1[threadIdx.x] = ((const float4*)bK1)[threadIdx.x];
        sb2[threadIdx.x] = ((const float4*)bK2)[threadIdx.x];
        sb3[threadIdx.x] = ((const float4*)bK3)[threadIdx.x];
    }
    __syncthreads();
    int i = blockIdx.x * 128 + threadIdx.x;
    if (i >= n) return;

    float p[32];
    const float4* Sp = (const float4*)(g_S + (size_t)i * 64);
#pragma unroll
    for (int k4 = 0; k4 < 8; k4++) {
        float4 v = Sp[8 + k4];
        p[4*k4] = v.x; p[4*k4+1] = v.y; p[4*k4+2] = v.z; p[4*k4+3] = v.w;
    }
    float dg = g_deg[i];

    float hK[32];
#pragma unroll
    for (int jb = 0; jb < 8; jb++) {
        float4 b = sbe[jb];
        float4 acc = make_float4(dg*b.x, dg*b.y, dg*b.z, dg*b.w);
#pragma unroll
        for (int k = 0; k < 32; k++) fma4(acc, p[k], sWe[k*8 + jb]);
        hK[4*jb] = acc.x; hK[4*jb+1] = acc.y; hK[4*jb+2] = acc.z; hK[4*jb+3] = acc.w;
    }

    float t1[64];
#pragma unroll
    for (int jb = 0; jb < 16; jb++) {
        float4 acc = sb1[jb];
#pragma unroll
        for (int k = 0; k < 32; k++) fma4(acc, hK[k], sW1[k*16 + jb]);
        t1[4*jb]   = tanh_fast(acc.x); t1[4*jb+1] = tanh_fast(acc.y);
        t1[4*jb+2] = tanh_fast(acc.z); t1[4*jb+3] = tanh_fast(acc.w);
    }

    float t2[64];
#pragma unroll
    for (int jb = 0; jb < 16; jb++) {
        float4 acc = sb2[jb];
#pragma unroll
        for (int k = 0; k < 64; k++) fma4(acc, t1[k], sW2[k*16 + jb]);
        t2[4*jb]   = fmaxf(acc.x, 0.f); t2[4*jb+1] = fmaxf(acc.y, 0.f);
        t2[4*jb+2] = fmaxf(acc.z, 0.f); t2[4*jb+3] = fmaxf(acc.w, 0.f);
    }

    float4* Eo = (float4*)(g_En + (size_t)i * 64);
#pragma unroll
    for (int jb = 0; jb < 16; jb++) {
        float4 acc = sb3[jb];
#pragma unroll
        for (int k = 0; k < 64; k++) fma4(acc, t2[k], sW3[k*16 + jb]);
        Eo[jb] = acc;
    }
}

// =============== kernel 4: mma.sync BF16 edge MLP =========================
// Round-12 shape (8 warps x m16 strips, tile = 128 edges) with the datapath
// in bf16: m16n8k16 -> mma count and b-frag LDS.64s HALVE; sA bytes halve;
// interlayer stores become conflict-free STS.32 (word = 4g+m+4nc).
// f32 kept for: bias (c-frag init), En multiply, atomics.
static constexpr int TILE_E = 128;
static constexpr int SAW = 36;          // b32 words per sA row (64 bf16 + pad)
// smem map (bytes)
static constexpr int OFF_WF1 = 0;        // 16 frags x 256B = 4096
static constexpr int OFF_WF2 = 4096;     // 32 frags x 256B = 8192
static constexpr int OFF_WF3 = 12288;    // 32 frags        = 8192
static constexpr int OFF_B1  = 20480;    // 64 f32
static constexpr int OFF_B2  = 20736;
static constexpr int OFF_B3  = 20992;
static constexpr int OFF_A   = 21248;    // 128 rows x 144B = 18432
static constexpr int EDGE_SMEM = OFF_A + TILE_E * SAW * 4;   // 39680

__device__ __forceinline__ void mma_bf16(float c[4], uint32_t a0, uint32_t a1,
                                         uint32_t a2, uint32_t a3,
                                         uint32_t b0, uint32_t b1) {
    asm volatile(
        "mma.sync.aligned.m16n8k16.row.col.f32.bf16.bf16.f32 "
        "{%0,%1,%2,%3}, {%4,%5,%6,%7}, {%8,%9}, {%0,%1,%2,%3};"
        : "+f"(c[0]), "+f"(c[1]), "+f"(c[2]), "+f"(c[3])
        : "r"(a0), "r"(a1), "r"(a2), "r"(a3), "r"(b0), "r"(b1));
}

// one layer: c[nc][4] = bias + A(rows rowBase..+15) @ W ; KC16 = K/16
template<int KC16>
__device__ __forceinline__ void layer_mma(float c[8][4], const uint32_t* sAw,
                                          const uint2* sWf, const float* sbias,
                                          int rowBase, int lane)
{
    int g = lane >> 2, m = lane & 3;
#pragma unroll
    for (int nc = 0; nc < 8; nc++) {
        float b0 = sbias[nc*8 + 2*m], b1 = sbias[nc*8 + 2*m + 1];
        c[nc][0] = b0; c[nc][1] = b1; c[nc][2] = b0; c[nc][3] = b1;
    }
    const uint32_t* ra = sAw + (rowBase + g) * SAW;
    const uint32_t* rb = ra + 8 * SAW;
#pragma unroll
    for (int kc = 0; kc < KC16; kc++) {
        int j = kc*8 + m;
        uint32_t a0 = ra[j];
        uint32_t a1 = rb[j];
        uint32_t a2 = ra[j + 4];
        uint32_t a3 = rb[j + 4];
#pragma unroll
        for (int nc = 0; nc < 8; nc++) {
            uint2 bb = sWf[(kc*8 + nc) * 32 + lane];
            mma_bf16(c[nc], a0, a1, a2, a3, bb.x, bb.y);
        }
    }
}

__global__ void __launch_bounds__(256, 3) edge_mlp(
    const int* __restrict__ src, const int* __restrict__ dst,
    const float* __restrict__ WU1, const float* __restrict__ bU1,
    const float* __restrict__ WU2, const float* __restrict__ bU2,
    const float* __restrict__ WU3, const float* __restrict__ bU3, int e_total)
{
    extern __shared__ char smem[];
    uint2* sWf1 = (uint2*)(smem + OFF_WF1);
    uint2* sWf2 = (uint2*)(smem + OFF_WF2);
    uint2* sWf3 = (uint2*)(smem + OFF_WF3);
    float* sb1 = (float*)(smem + OFF_B1);
    float* sb2 = (float*)(smem + OFF_B2);
    float* sb3 = (float*)(smem + OFF_B3);
    uint32_t* sAw = (uint32_t*)(smem + OFF_A);

    int tid = threadIdx.x;

    // ---- weights -> bf16 fragment order ----
    // frag f = kc*8+nc; lane (g = lane>>2, m = lane&3) holds
    //   b.x = {W[kc*16+2m][n], W[kc*16+2m+1][n]}  (n = nc*8+g)
    //   b.y = {W[kc*16+2m+8][n], W[kc*16+2m+9][n]}
    for (int i = tid; i < 16 * 32; i += 256) {        // layer1: K=32 -> 2 kc
        int lane_ = i & 31, f = i >> 5;
        int g_ = lane_ >> 2, m_ = lane_ & 3;
        int n0 = (f & 7) * 8 + g_;
        int k0 = (f >> 3) * 16 + 2*m_;
        uint2 b;
        b.x = pack_bf(__ldg(WU1 + k0*64 + n0),     __ldg(WU1 + (k0+1)*64 + n0));
        b.y = pack_bf(__ldg(WU1 + (k0+8)*64 + n0), __ldg(WU1 + (k0+9)*64 + n0));
        sWf1[i] = b;
    }
    for (int i = tid; i < 32 * 32; i += 256) {        // layers 2,3: K=64 -> 4 kc
        int lane_ = i & 31, f = i >> 5;
        int g_ = lane_ >> 2, m_ = lane_ & 3;
        int n0 = (f & 7) * 8 + g_;
        int k0 = (f >> 3) * 16 + 2*m_;
        uint2 b2v, b3v;
        b2v.x = pack_bf(__ldg(WU2 + k0*64 + n0),     __ldg(WU2 + (k0+1)*64 + n0));
        b2v.y = pack_bf(__ldg(WU2 + (k0+8)*64 + n0), __ldg(WU2 + (k0+9)*64 + n0));
        b3v.x = pack_bf(__ldg(WU3 + k0*64 + n0),     __ldg(WU3 + (k0+1)*64 + n0));
        b3v.y = pack_bf(__ldg(WU3 + (k0+8)*64 + n0), __ldg(WU3 + (k0+9)*64 + n0));
        sWf2[i] = b2v;
        sWf3[i] = b3v;
    }
    if (tid < 64) {
        sb1[tid] = __ldg(bU1 + tid);
        sb2[tid] = __ldg(bU2 + tid);
        sb3[tid] = __ldg(bU3 + tid);
    }
    __syncthreads();

    int lane = tid & 31, w = tid >> 5;
    int rowBase = w * 16;
    int g = lane >> 2, m = lane & 3;
    int eh = tid & 127, half = tid >> 7;   // gather roles

    int ntiles = (e_total + TILE_E - 1) / TILE_E;
    for (int t = blockIdx.x; t < ntiles; t += gridDim.x) {
        int base = t * TILE_E;

        // ---- gather: A[eh] = bf16(h1[src]+h2[dst]), cols half*16..+15 ----
        {
            int ge = base + eh;
            bool valid = ge < e_total;
            int s = 0, d = 0;
            if (valid) { s = __ldg(src + ge); d = __ldg(dst + ge); }
            const float4* h1p = (const float4*)(g_h1 + (size_t)s * 32) + half * 4;
            const float4* h2p = (const float4*)(g_h2 + (size_t)d * 32) + half * 4;
            uint32_t o[8];
#pragma unroll
            for (int q = 0; q < 4; q++) {
                float4 a = __ldg(h1p + q), b = __ldg(h2p + q);
                float s0 = valid ? a.x + b.x : 0.f;
                float s1 = valid ? a.y + b.y : 0.f;
                float s2 = valid ? a.z + b.z : 0.f;
                float s3 = valid ? a.w + b.w : 0.f;
                o[2*q]   = pack_bf(s0, s1);
                o[2*q+1] = pack_bf(s2, s3);
            }
            uint32_t* rowp = sAw + eh * SAW + half * 8;
            *(uint4*)(rowp)     = make_uint4(o[0], o[1], o[2], o[3]);
            *(uint4*)(rowp + 4) = make_uint4(o[4], o[5], o[6], o[7]);
        }
        __syncthreads();

        float c[8][4];

        // ---- layer 1: K=32, tanh ----
        layer_mma<2>(c, sAw, sWf1, sb1, rowBase, lane);
        __syncthreads();
#pragma unroll
        for (int nc = 0; nc < 8; nc++) {
            int j = nc*4 + m;
            sAw[(rowBase + g) * SAW + j] =
                pack_bf(tanh_fast(c[nc][0]), tanh_fast(c[nc][1]));
            sAw[(rowBase + g + 8) * SAW + j] =
                pack_bf(tanh_fast(c[nc][2]), tanh_fast(c[nc][3]));
        }
        __syncthreads();

        // ---- layer 2: K=64, relu ----
        layer_mma<4>(c, sAw, sWf2, sb2, rowBase, lane);
        __syncthreads();
#pragma unroll
        for (int nc = 0; nc < 8; nc++) {
            int j = nc*4 + m;
            sAw[(rowBase + g) * SAW + j] =
                pack_bf(fmaxf(c[nc][0], 0.f), fmaxf(c[nc][1], 0.f));
            sAw[(rowBase + g + 8) * SAW + j] =
                pack_bf(fmaxf(c[nc][2], 0.f), fmaxf(c[nc][3], 0.f));
        }
        __syncthreads();

        // ---- layer 3: K=64 (bias via c-init), store raw ----
        layer_mma<4>(c, sAw, sWf3, sb3, rowBase, lane);
        __syncthreads();
#pragma unroll
        for (int nc = 0; nc < 8; nc++) {
            int j = nc*4 + m;
            sAw[(rowBase + g) * SAW + j]     = pack_bf(c[nc][0], c[nc][1]);
            sAw[(rowBase + g + 8) * SAW + j] = pack_bf(c[nc][2], c[nc][3]);
        }
        __syncthreads();

        // ---- epilogue: D3 * E_node[src] -> f32 atomic scatter ----
        {
            int ee = tid >> 1;
            int chw = (tid & 1) * 16;       // b32 col base (32 bf16 cols)
            if (base + ee < e_total) {
                int s = __ldg(src + base + ee);
                int d = __ldg(dst + base + ee);
                const float4* Enp =
                    (const float4*)(g_En + (size_t)s * 64 + chw * 2);
                float4* Ew = (float4*)(g_Enew + (size_t)d * 64 + chw * 2);
                const uint32_t* rowp = sAw + ee * SAW + chw;
#pragma unroll
                for (int q = 0; q < 4; q++) {
                    uint4 u = ((const uint4*)rowp)[q];
                    float2 v0 = unpack_bf(u.x), v1 = unpack_bf(u.y);
                    float2 v2 = unpack_bf(u.z), v3 = unpack_bf(u.w);
                    float4 EnA = __ldg(Enp + 2*q);
                    float4 EnB = __ldg(Enp + 2*q + 1);
                    float4 r0 = make_float4(v0.x*EnA.x, v0.y*EnA.y,
                                            v1.x*EnA.z, v1.y*EnA.w);
                    float4 r1 = make_float4(v2.x*EnB.x, v2.y*EnB.y,
                                            v3.x*EnB.z, v3.y*EnB.w);
                    atomicAdd(Ew + 2*q,     r0);
                    atomicAdd(Ew + 2*q + 1, r1);
                }
            }
        }
        __syncthreads();   // protect sA before next tile's gather
    }
}

// ------ kernel 5: dH = E_new@WH + bH ; d_agg = S@WD[:,32:] + deg*b ; out -
__global__ __launch_bounds__(128) void node_post(
    const float* __restrict__ WH, const float* __restrict__ bH,
    const float* __restrict__ WD, const float* __restrict__ bD,
    float* __restrict__ out, int n)
{
    __shared__ float4 sWH[64 * 16], sbH[16];
    __shared__ float4 sWD[64 * 8],  sbD[8];
    for (int i = threadIdx.x; i < 64 * 16; i += 128) sWH[i] = ((const float4*)WH)[i];
    for (int i = threadIdx.x; i < 64 * 8; i += 128) {
        int k = i >> 3, jb = i & 7;
        sWD[i] = ((const float4*)(WD + k * 64 + 32))[jb];
    }
    if (threadIdx.x < 16) sbH[threadIdx.x] = ((const float4*)bH)[threadIdx.x];
    if (threadIdx.x < 8)  sbD[threadIdx.x] = ((const float4*)(bD + 32))[threadIdx.x];
    __syncthreads();
    int i = blockIdx.x * 128 + threadIdx.x;
    if (i >= n) return;

    float En[64];
    const float4* Ep = (const float4*)(g_Enew + (size_t)i * 64);
#pragma unroll
    for (int k4 = 0; k4 < 16; k4++) {
        float4 v = Ep[k4];
        En[4*k4] = v.x; En[4*k4+1] = v.y; En[4*k4+2] = v.z; En[4*k4+3] = v.w;
    }

    float4* op = (float4*)(out + (size_t)i * 64);
    float dlo[32];
#pragma unroll
    for (int jb = 0; jb < 16; jb++) {
        float4 acc = sbH[jb];
#pragma unroll
        for (int k = 0; k < 64; k++) fma4(acc, En[k], sWH[k*16 + jb]);
        if (jb >= 8) {
            op[jb - 8] = acc;
        } else {
            dlo[4*jb] = acc.x; dlo[4*jb+1] = acc.y;
            dlo[4*jb+2] = acc.z; dlo[4*jb+3] = acc.w;
        }
    }

    float S[64];
    const float4* Sp = (const float4*)(g_S + (size_t)i * 64);
#pragma unroll
    for (int k4 = 0; k4 < 16; k4++) {
        float4 v = Sp[k4];
        S[4*k4] = v.x; S[4*k4+1] = v.y; S[4*k4+2] = v.z; S[4*k4+3] = v.w;
    }
    float dg = g_deg[i];
#pragma unroll
    for (int jb = 0; jb < 8; jb++) {
        float4 b = sbD[jb];
        float4 acc = make_float4(dg*b.x, dg*b.y, dg*b.z, dg*b.w);
#pragma unroll
        for (int k = 0; k < 64; k++) fma4(acc, S[k], sWD[k*8 + jb]);
        float4 o;
        o.x = -dlo[4*jb]   - acc.x;
        o.y = -dlo[4*jb+1] - acc.y;
        o.z = -dlo[4*jb+2] - acc.z;
        o.w = -dlo[4*jb+3] - acc.w;
        op[8 + jb] = o;
    }
}

// -------------------------------------------------------------------------
extern "C" void kernel_launch(void* const* d_in, const int* in_sizes, int n_in,
                              void* d_out, int out_size)
{
    const float* x      = (const float*)d_in[0];
    const int*   src    = (const int*)  d_in[1];
    const int*   dst    = (const int*)  d_in[2];
    const float* WencK  = (const float*)d_in[3];
    const float* bencK  = (const float*)d_in[4];
    const float* WencP1 = (const float*)d_in[5];
    const float* bencP1 = (const float*)d_in[6];
    const float* WencP2 = (const float*)d_in[7];
    const float* bencP2 = (const float*)d_in[8];
    const float* WK1 = (const float*)d_in[9];
    const float* bK1 = (const float*)d_in[10];
    const float* WK2 = (const float*)d_in[11];
    const float* bK2 = (const float*)d_in[12];
    const float* WK3 = (const float*)d_in[13];
    const float* bK3 = (const float*)d_in[14];
    const float* WU1 = (const float*)d_in[15];
    const float* bU1 = (const float*)d_in[16];
    const float* WU2 = (const float*)d_in[17];
    const float* bU2 = (const float*)d_in[18];
    const float* WU3 = (const float*)d_in[19];
    const float* bU3 = (const float*)d_in[20];
    const float* WH  = (const float*)d_in[21];
    const float* bH  = (const float*)d_in[22];
    const float* WD  = (const float*)d_in[23];
    const float* bD  = (const float*)d_in[24];

    int n = in_sizes[0] / 64;
    int e = in_sizes[1];
    if (n > MAXN) n = MAXN;

    cudaFuncSetAttribute(edge_mlp, cudaFuncAttributeMaxDynamicSharedMemorySize,
                         EDGE_SMEM);

    void *pS, *pdeg, *pEnew;
    cudaGetSymbolAddress(&pS,    g_S);
    cudaGetSymbolAddress(&pdeg,  g_deg);
    cudaGetSymbolAddress(&pEnew, g_Enew);
    cudaMemsetAsync(pS,    0, (size_t)n * 64 * sizeof(float));
    cudaMemsetAsync(pdeg,  0, (size_t)n * sizeof(float));
    cudaMemsetAsync(pEnew, 0, (size_t)n * 64 * sizeof(float));

    int nb = (n + 127) / 128;
    node_pre<<<nb, 128>>>(x, WencP1, bencP1, WencP2, bencP2, n);
    edge_scatter<<<((size_t)e * 16 + 255) / 256, 256>>>(x, src, dst, e);
    node_mid<<<nb, 128>>>(WencK, bencK, WK1, bK1, WK2, bK2, WK3, bK3, n);
    edge_mlp<<<444, 256, EDGE_SMEM>>>(src, dst, WU1, bU1, WU2, bU2, WU3, bU3, e);
    node_post<<<nb, 128>>>(WH, bH, WD, bD, (float*)d_out, n);
}